// round 2
// baseline (speedup 1.0000x reference)
#include <cuda_runtime.h>

// LargeMarginLoss: linear head => Jacobian J[i] = W^T (batch-independent).
// dual_norm[i,c] = sqrt(n[c] + n[t_i] - 2*W_c.W_{t_i} + eps) + eps
// loss = mean_i max_{c != t_i} relu(gamma + (logits[i,c]-logits[i,t_i]) / dual_norm[i,c])

#define GAMMA_ 10.0f
#define EPS_   1e-6f

constexpr int Bn = 128;   // batch
constexpr int Dn = 1024;  // feature dim
constexpr int Cn = 1000;  // classes
constexpr int Mn = 256;   // stacked rows: 128 activations + 128 gathered W columns

// scratch (device globals; no allocation allowed)
__device__ float g_norm[Cn];        // column norms of W
__device__ float g_U[Bn * Dn];      // U[i][d] = W[d][t_i]
__device__ float g_P[Mn * Cn];      // rows 0..127: A@W ; rows 128..255: U@W

// ---------------- K0: zero scratch + output ----------------
__global__ void k0_zero(float* out) {
    int idx = blockIdx.x * blockDim.x + threadIdx.x;
    int stride = gridDim.x * blockDim.x;
    for (int i = idx; i < Mn * Cn; i += stride) g_P[i] = 0.0f;
    for (int i = idx; i < Cn; i += stride) g_norm[i] = 0.0f;
    if (idx == 0) out[0] = 0.0f;
}

// ---------------- K1: column norms (blocks 0..127) + target-column gather (blocks 128..255) ----
__global__ void k1_norm_gather(const float* __restrict__ W, const int* __restrict__ targets) {
    int bid = blockIdx.x;
    if (bid < 128) {
        // 8 rows of W per block, coalesced over c
        int d0 = bid * 8;
        for (int c = threadIdx.x; c < Cn; c += blockDim.x) {
            float acc = 0.0f;
#pragma unroll
            for (int dd = 0; dd < 8; ++dd) {
                float w = W[(d0 + dd) * Cn + c];
                acc = fmaf(w, w, acc);
            }
            atomicAdd(&g_norm[c], acc);
        }
    } else {
        int i = bid - 128;
        int t = targets[i];
        for (int d = threadIdx.x; d < Dn; d += blockDim.x)
            g_U[i * Dn + d] = W[d * Cn + t];
    }
}

// ---------------- K2: GEMM [256,1024] x [1024,1000] with split-K, atomic reduce into g_P ----
constexpr int BM = 64, BN = 64, BK = 16, SPLITK = 4;
constexpr int KCHUNK = Dn / SPLITK;  // 256

__global__ __launch_bounds__(256) void k2_gemm(const float* __restrict__ A,
                                               const float* __restrict__ W) {
    __shared__ __align__(16) float As[BM][BK + 1];   // [64][17]
    __shared__ __align__(16) float Bs[BK][BN + 4];   // [16][68]

    const int tx = threadIdx.x % 16;   // n microtile
    const int ty = threadIdx.x / 16;   // m microtile
    const int n0 = blockIdx.x * BN;
    const int m0 = blockIdx.y * BM;
    const int kbase = blockIdx.z * KCHUNK;

    // A-tile load mapping: one float4 along k per thread
    const int lm  = threadIdx.x / 4;        // 0..63
    const int lkq = threadIdx.x % 4;        // 0..3 (float4 within 16 k)
    const int gm  = m0 + lm;
    const float* lrow = (gm < 128) ? (A + (size_t)gm * Dn)
                                   : (g_U + (size_t)(gm - 128) * Dn);

    // B-tile load mapping: one float4 along n per thread
    const int lk  = threadIdx.x / 16;       // 0..15
    const int lnq = threadIdx.x % 16;       // 0..15
    const int gn4 = n0 + lnq * 4;
    const bool nvalid = (gn4 < Cn);         // Cn % 4 == 0, so whole-vec validity

    float acc[4][4] = {};

    for (int kt = 0; kt < KCHUNK; kt += BK) {
        const int k0 = kbase + kt;
        float4 av = *(const float4*)(lrow + k0 + lkq * 4);
        float4 bv = nvalid ? *(const float4*)(W + (size_t)(k0 + lk) * Cn + gn4)
                           : make_float4(0.f, 0.f, 0.f, 0.f);
        __syncthreads();
        As[lm][lkq * 4 + 0] = av.x;
        As[lm][lkq * 4 + 1] = av.y;
        As[lm][lkq * 4 + 2] = av.z;
        As[lm][lkq * 4 + 3] = av.w;
        *(float4*)&Bs[lk][lnq * 4] = bv;
        __syncthreads();

#pragma unroll
        for (int kk = 0; kk < BK; ++kk) {
            float4 bf = *(const float4*)&Bs[kk][tx * 4];
#pragma unroll
            for (int i = 0; i < 4; ++i) {
                float a = As[ty * 4 + i][kk];
                acc[i][0] = fmaf(a, bf.x, acc[i][0]);
                acc[i][1] = fmaf(a, bf.y, acc[i][1]);
                acc[i][2] = fmaf(a, bf.z, acc[i][2]);
                acc[i][3] = fmaf(a, bf.w, acc[i][3]);
            }
        }
    }

#pragma unroll
    for (int i = 0; i < 4; ++i) {
        int gmr = m0 + ty * 4 + i;
#pragma unroll
        for (int j = 0; j < 4; ++j) {
            int gn = n0 + tx * 4 + j;
            if (gn < Cn) atomicAdd(&g_P[(size_t)gmr * Cn + gn], acc[i][j]);
        }
    }
}

// ---------------- K3: per-row margin-violation max, mean into out ----------------
__global__ void k3_loss(const float* __restrict__ bvec, const int* __restrict__ targets,
                        float* __restrict__ out) {
    const int i = blockIdx.x;
    const int t = targets[i];
    const float nt = g_norm[t];
    const float corr = g_P[(size_t)i * Cn + t] + bvec[t];

    float vmax = 0.0f;
    for (int c = threadIdx.x; c < Cn; c += blockDim.x) {
        float lg = g_P[(size_t)i * Cn + c] + bvec[c];
        float gt = g_P[(size_t)(i + 128) * Cn + c];
        float ss = g_norm[c] + nt - 2.0f * gt;
        float dn = sqrtf(ss + EPS_) + EPS_;
        float v = fmaxf(0.0f, GAMMA_ + (lg - corr) / dn);
        if (c == t) v = 0.0f;
        vmax = fmaxf(vmax, v);
    }

    __shared__ float red[256];
    red[threadIdx.x] = vmax;
    __syncthreads();
    for (int s = 128; s > 0; s >>= 1) {
        if (threadIdx.x < s) red[threadIdx.x] = fmaxf(red[threadIdx.x], red[threadIdx.x + s]);
        __syncthreads();
    }
    if (threadIdx.x == 0) atomicAdd(out, red[0] * (1.0f / 128.0f));
}

// ---------------- launch ----------------
extern "C" void kernel_launch(void* const* d_in, const int* in_sizes, int n_in,
                              void* d_out, int out_size) {
    const float* A = (const float*)d_in[0];        // activations [128,1024]
    const float* W = (const float*)d_in[1];        // W [1024,1000]
    const float* b = (const float*)d_in[2];        // b [1000]
    const int* targets = (const int*)d_in[3];      // [128]
    float* out = (float*)d_out;

    k0_zero<<<256, 256>>>(out);
    k1_norm_gather<<<256, 256>>>(W, targets);
    k2_gemm<<<dim3(16, 4, SPLITK), 256>>>(A, W);
    k3_loss<<<128, 256>>>(b, targets, out);
}

// round 4
// speedup vs baseline: 1.6525x; 1.6525x over previous
#include <cuda_runtime.h>

#define GAMMA_ 10.0f
#define EPS_   1e-6f

constexpr int Dn = 1024;  // feature dim (K)
constexpr int Cn = 1000;  // classes
constexpr int Bn = 128;   // batch

// ---------------- device scratch (tf32 values stored as u32) ----------------
__device__ unsigned g_Atf[128 * 1024];     // activations, tf32
__device__ unsigned g_Utf[128 * 1024];     // gathered target columns W[:,t_i], tf32
__device__ unsigned g_Wtf[1024 * 1024];    // W padded [k][c], cols 1000..1023 = 0, tf32
__device__ float    g_norm[Cn];            // exact fp32 column norms
__device__ float    g_P[2][256][1024];     // split-K slabs: rows 0..127 logits, 128..255 gram

__device__ __forceinline__ unsigned f2tf(float x) {
    unsigned u;
    asm("cvt.rna.tf32.f32 %0, %1;" : "=r"(u) : "f"(x));
    return u;
}

// ---------------- k1: norms + gather + tf32 conversion + zero out ----------------
// blocks 0..124: norms (8 classes each)
// blocks 125..252: gather U rows (tf32)
// blocks 253..1276: W row k -> g_Wtf padded
// blocks 1277..1404: A -> tf32
__global__ void k1_prep(const float* __restrict__ W, const float* __restrict__ A,
                        const int* __restrict__ targets, float* __restrict__ out) {
    __shared__ float s[8][2][4];
    const int bid = blockIdx.x, tid = threadIdx.x;

    if (bid < 125) {
        const int c0 = bid * 8;
        const int half = tid & 1, r0 = tid >> 1;
        float a0 = 0.f, a1 = 0.f, a2 = 0.f, a3 = 0.f;
        for (int r = r0; r < 1024; r += 128) {
            float4 v = *(const float4*)(W + r * Cn + c0 + 4 * half);
            a0 = fmaf(v.x, v.x, a0); a1 = fmaf(v.y, v.y, a1);
            a2 = fmaf(v.z, v.z, a2); a3 = fmaf(v.w, v.w, a3);
        }
#pragma unroll
        for (int o = 16; o >= 2; o >>= 1) {
            a0 += __shfl_xor_sync(~0u, a0, o); a1 += __shfl_xor_sync(~0u, a1, o);
            a2 += __shfl_xor_sync(~0u, a2, o); a3 += __shfl_xor_sync(~0u, a3, o);
        }
        const int wid = tid >> 5, l = tid & 31;
        if (l < 2) { s[wid][l][0] = a0; s[wid][l][1] = a1; s[wid][l][2] = a2; s[wid][l][3] = a3; }
        __syncthreads();
        if (tid < 8) {
            float t = 0.f;
#pragma unroll
            for (int w = 0; w < 8; ++w) t += s[w][tid >> 2][tid & 3];
            g_norm[c0 + tid] = t;
        }
        if (bid == 0 && tid == 0) out[0] = 0.0f;
    } else if (bid < 253) {
        const int i = bid - 125;
        const int t = targets[i];
        for (int k = tid; k < 1024; k += 256)
            g_Utf[i * 1024 + k] = f2tf(W[k * Cn + t]);
    } else if (bid < 1277) {
        const int k = bid - 253;
        if (tid < 250) {
            float4 v = *(const float4*)(W + k * Cn + tid * 4);
            uint4 u;
            u.x = f2tf(v.x); u.y = f2tf(v.y); u.z = f2tf(v.z); u.w = f2tf(v.w);
            *(uint4*)(g_Wtf + k * 1024 + tid * 4) = u;
        } else if (tid < 256) {
            uint4 z = {0u, 0u, 0u, 0u};
            *(uint4*)(g_Wtf + k * 1024 + 1000 + (tid - 250) * 4) = z;
        }
    } else {
        const int i = (bid - 1277) * 256 + tid;   // float4 index into A (32768 total)
        float4 v = ((const float4*)A)[i];
        uint4 u;
        u.x = f2tf(v.x); u.y = f2tf(v.y); u.z = f2tf(v.z); u.w = f2tf(v.w);
        ((uint4*)g_Atf)[i] = u;
    }
}

// ---------------- k2: tf32 mma.sync GEMM, CTA 64x64, split-K=2 ----------------
constexpr int PA = 36;   // (4r+c)%32 bijective -> conflict-free A frag loads
constexpr int PB = 72;   // (8k+n)%32 bijective -> conflict-free B frag loads

__global__ __launch_bounds__(128) void k2_gemm() {
    __shared__ __align__(16) unsigned As[2][64][PA];
    __shared__ __align__(16) unsigned Bs[2][32][PB];

    const int tid = threadIdx.x, lane = tid & 31, wid = tid >> 5;
    const int wm = wid & 1, wn = wid >> 1;
    const int n0 = blockIdx.x * 64;
    const int mb = blockIdx.y;     // 0..3 : m-tile (0,1 = activations; 2,3 = gathered U)
    const int kb = blockIdx.z;     // split-K half
    const unsigned* Asrc = (mb < 2) ? (g_Atf + mb * 64 * 1024)
                                    : (g_Utf + (mb - 2) * 64 * 1024);
    const int kbase = kb * 512;

    float acc[2][4][4];
#pragma unroll
    for (int i = 0; i < 2; ++i)
#pragma unroll
        for (int j = 0; j < 4; ++j)
#pragma unroll
            for (int k = 0; k < 4; ++k) acc[i][j][k] = 0.f;

    uint4 pa[4], pb[4];
    auto ldchunk = [&](int kc) {
        const int k0 = kbase + kc * 32;
#pragma unroll
        for (int p = 0; p < 4; ++p) {
            int i = tid + 128 * p;
            int row = i >> 3, kq = i & 7;
            pa[p] = *(const uint4*)(Asrc + row * 1024 + k0 + kq * 4);
            int r = i >> 4, nq = i & 15;
            pb[p] = *(const uint4*)(g_Wtf + (k0 + r) * 1024 + n0 + nq * 4);
        }
    };
    auto stchunk = [&](int bf) {
#pragma unroll
        for (int p = 0; p < 4; ++p) {
            int i = tid + 128 * p;
            int row = i >> 3, kq = i & 7;
            *(uint4*)&As[bf][row][kq * 4] = pa[p];
            int r = i >> 4, nq = i & 15;
            *(uint4*)&Bs[bf][r][nq * 4] = pb[p];
        }
    };

    ldchunk(0);
    stchunk(0);
    __syncthreads();

    for (int ch = 0; ch < 16; ++ch) {
        if (ch < 15) ldchunk(ch + 1);
        const int bf = ch & 1;
        const int gid = lane >> 2, q = lane & 3;
#pragma unroll
        for (int ks = 0; ks < 4; ++ks) {
            const int col = ks * 8 + q;
            unsigned a[2][4], b[4][2];
#pragma unroll
            for (int mf = 0; mf < 2; ++mf) {
                int r = wm * 32 + mf * 16 + gid;
                a[mf][0] = As[bf][r][col];
                a[mf][1] = As[bf][r + 8][col];
                a[mf][2] = As[bf][r][col + 4];
                a[mf][3] = As[bf][r + 8][col + 4];
            }
#pragma unroll
            for (int nf = 0; nf < 4; ++nf) {
                int nn = wn * 32 + nf * 8 + gid;
                b[nf][0] = Bs[bf][col][nn];
                b[nf][1] = Bs[bf][col + 4][nn];
            }
#pragma unroll
            for (int mf = 0; mf < 2; ++mf)
#pragma unroll
                for (int nf = 0; nf < 4; ++nf)
                    asm volatile(
                        "mma.sync.aligned.m16n8k8.row.col.f32.tf32.tf32.f32 "
                        "{%0,%1,%2,%3},{%4,%5,%6,%7},{%8,%9},{%0,%1,%2,%3};"
                        : "+f"(acc[mf][nf][0]), "+f"(acc[mf][nf][1]),
                          "+f"(acc[mf][nf][2]), "+f"(acc[mf][nf][3])
                        : "r"(a[mf][0]), "r"(a[mf][1]), "r"(a[mf][2]), "r"(a[mf][3]),
                          "r"(b[nf][0]), "r"(b[nf][1]));
        }
        if (ch < 15) {
            __syncthreads();
            stchunk((ch + 1) & 1);
            __syncthreads();
        }
    }

    // epilogue: plain stores into this split-K slab (no atomics)
    const int m0 = mb * 64, gid = lane >> 2, q = lane & 3;
#pragma unroll
    for (int mf = 0; mf < 2; ++mf) {
        int row = m0 + wm * 32 + mf * 16 + gid;
#pragma unroll
        for (int nf = 0; nf < 4; ++nf) {
            int coln = n0 + wn * 32 + nf * 8 + 2 * q;
            *(float2*)&g_P[kb][row][coln]     = make_float2(acc[mf][nf][0], acc[mf][nf][1]);
            *(float2*)&g_P[kb][row + 8][coln] = make_float2(acc[mf][nf][2], acc[mf][nf][3]);
        }
    }
}

// ---------------- k3: per-row max violation, mean into out ----------------
__global__ __launch_bounds__(1024) void k3_loss(const float* __restrict__ bvec,
                                                const int* __restrict__ targets,
                                                float* __restrict__ out) {
    const int i = blockIdx.x;
    const int c = threadIdx.x;
    const int t = targets[i];
    __shared__ float s_corr, s_nt;
    __shared__ float red[32];

    if (c == 0) {
        s_corr = g_P[0][i][t] + g_P[1][i][t] + bvec[t];
        s_nt = g_norm[t];
    }
    __syncthreads();

    float v = 0.0f;
    if (c < Cn && c != t) {
        float lg = g_P[0][i][c] + g_P[1][i][c] + bvec[c];
        float gr = g_P[0][i + 128][c] + g_P[1][i + 128][c];
        float ss = g_norm[c] + s_nt - 2.0f * gr;
        float dn = sqrtf(ss + EPS_) + EPS_;
        v = fmaxf(0.0f, GAMMA_ + (lg - s_corr) / dn);
    }
#pragma unroll
    for (int o = 16; o; o >>= 1) v = fmaxf(v, __shfl_xor_sync(~0u, v, o));
    if ((c & 31) == 0) red[c >> 5] = v;
    __syncthreads();
    if (c < 32) {
        float r = red[c];
#pragma unroll
        for (int o = 16; o; o >>= 1) r = fmaxf(r, __shfl_xor_sync(~0u, r, o));
        if (c == 0) atomicAdd(out, r * (1.0f / 128.0f));
    }
}

// ---------------- launch ----------------
extern "C" void kernel_launch(void* const* d_in, const int* in_sizes, int n_in,
                              void* d_out, int out_size) {
    const float* A = (const float*)d_in[0];        // [128,1024]
    const float* W = (const float*)d_in[1];        // [1024,1000]
    const float* b = (const float*)d_in[2];        // [1000]
    const int* targets = (const int*)d_in[3];      // [128]
    float* out = (float*)d_out;

    k1_prep<<<1405, 256>>>(W, A, targets, out);
    k2_gemm<<<dim3(16, 4, 2), 128>>>();
    k3_loss<<<Bn, 1024>>>(b, targets, out);
}

// round 5
// speedup vs baseline: 1.6651x; 1.0076x over previous
#include <cuda_runtime.h>

#define GAMMA_ 10.0f
#define EPS_   1e-6f

constexpr int Cn = 1000;  // classes
constexpr int Bn = 128;   // batch
constexpr int SPLITK = 4;

// ---------------- device scratch ----------------
__device__ float g_U[128 * 1024];          // gathered target columns W[:,t_i] (fp32)
__device__ float g_npart[32][1024];        // 32-way row-split column-norm partials
__device__ float g_norm[1024];             // reduced column norms
__device__ float g_P[SPLITK][256][1024];   // split-K slabs: rows 0..127 logits, 128..255 gram

// ---------------- k1: norms (coalesced) + gather + zero out ----------------
// blocks 0..255  : norm partials (rowchunk = bid>>3, colblock = bid&7)
// blocks 256..383: gather U rows
// block  384     : zero out
__global__ __launch_bounds__(128) void k1_prep(const float* __restrict__ W,
                                               const int* __restrict__ targets,
                                               float* __restrict__ out) {
    const int bid = blockIdx.x, tid = threadIdx.x;
    if (bid < 256) {
        const int rc = bid >> 3, cb = bid & 7;
        const int c = cb * 128 + tid;
        if (c < Cn) {
            float acc = 0.0f;
#pragma unroll
            for (int j = 0; j < 32; ++j) {
                float w = W[(rc * 32 + j) * Cn + c];
                acc = fmaf(w, w, acc);
            }
            g_npart[rc][c] = acc;
        }
    } else if (bid < 384) {
        const int i = bid - 256;
        const int t = targets[i];
#pragma unroll
        for (int j = 0; j < 8; ++j) {
            int k = tid + 128 * j;
            g_U[i * 1024 + k] = W[k * Cn + t];
        }
    } else if (tid == 0) {
        out[0] = 0.0f;
    }
}

// ---------------- k2: tf32 mma.sync GEMM (raw fp32 bits), CTA 64x64, split-K=4 ----
constexpr int PA = 36;   // (4r+c)%32 bijective -> conflict-free A frag loads
constexpr int PB = 72;   // (8k+n)%32 bijective -> conflict-free B frag loads

__global__ __launch_bounds__(128) void k2_gemm(const float* __restrict__ A,
                                               const float* __restrict__ W) {
    const int tid = threadIdx.x;
    const int mb = blockIdx.y;

    // extra lane of the grid: reduce norm partials (overlaps with GEMM blocks)
    if (mb == 4) {
        if (blockIdx.x < 8 && blockIdx.z == 0) {
            int c = blockIdx.x * 128 + tid;
            if (c < Cn) {
                float s = 0.0f;
#pragma unroll
                for (int r = 0; r < 32; ++r) s += g_npart[r][c];
                g_norm[c] = s;
            }
        }
        return;
    }

    __shared__ __align__(16) unsigned As[2][64][PA];
    __shared__ __align__(16) unsigned Bs[2][32][PB];

    const int lane = tid & 31, wid = tid >> 5;
    const int wm = wid & 1, wn = wid >> 1;
    const int n0 = blockIdx.x * 64;
    const int kb = blockIdx.z;
    const float* Asrc = (mb < 2) ? (A + mb * 64 * 1024) : (g_U + (mb - 2) * 64 * 1024);
    const int kbase = kb * 256;

    float acc[2][4][4];
#pragma unroll
    for (int i = 0; i < 2; ++i)
#pragma unroll
        for (int j = 0; j < 4; ++j)
#pragma unroll
            for (int k = 0; k < 4; ++k) acc[i][j][k] = 0.f;

    uint4 pa[4], pb[4];
    auto ldchunk = [&](int kc) {
        const int k0 = kbase + kc * 32;
#pragma unroll
        for (int p = 0; p < 4; ++p) {
            int i = tid + 128 * p;
            int row = i >> 3, kq = i & 7;
            pa[p] = *(const uint4*)(Asrc + row * 1024 + k0 + kq * 4);
            int r = i >> 4, nq = i & 15;
            int gc = n0 + nq * 4;
            pb[p] = (gc < Cn) ? *(const uint4*)(W + (k0 + r) * Cn + gc)
                              : make_uint4(0u, 0u, 0u, 0u);
        }
    };
    auto stchunk = [&](int bf) {
#pragma unroll
        for (int p = 0; p < 4; ++p) {
            int i = tid + 128 * p;
            int row = i >> 3, kq = i & 7;
            *(uint4*)&As[bf][row][kq * 4] = pa[p];
            int r = i >> 4, nq = i & 15;
            *(uint4*)&Bs[bf][r][nq * 4] = pb[p];
        }
    };

    ldchunk(0);
    stchunk(0);
    __syncthreads();

    for (int ch = 0; ch < 8; ++ch) {
        if (ch < 7) ldchunk(ch + 1);
        const int bf = ch & 1;
        const int gid = lane >> 2, q = lane & 3;
#pragma unroll
        for (int ks = 0; ks < 4; ++ks) {
            const int col = ks * 8 + q;
            unsigned a[2][4], b[4][2];
#pragma unroll
            for (int mf = 0; mf < 2; ++mf) {
                int r = wm * 32 + mf * 16 + gid;
                a[mf][0] = As[bf][r][col];
                a[mf][1] = As[bf][r + 8][col];
                a[mf][2] = As[bf][r][col + 4];
                a[mf][3] = As[bf][r + 8][col + 4];
            }
#pragma unroll
            for (int nf = 0; nf < 4; ++nf) {
                int nn = wn * 32 + nf * 8 + gid;
                b[nf][0] = Bs[bf][col][nn];
                b[nf][1] = Bs[bf][col + 4][nn];
            }
#pragma unroll
            for (int mf = 0; mf < 2; ++mf)
#pragma unroll
                for (int nf = 0; nf < 4; ++nf)
                    asm volatile(
                        "mma.sync.aligned.m16n8k8.row.col.f32.tf32.tf32.f32 "
                        "{%0,%1,%2,%3},{%4,%5,%6,%7},{%8,%9},{%0,%1,%2,%3};"
                        : "+f"(acc[mf][nf][0]), "+f"(acc[mf][nf][1]),
                          "+f"(acc[mf][nf][2]), "+f"(acc[mf][nf][3])
                        : "r"(a[mf][0]), "r"(a[mf][1]), "r"(a[mf][2]), "r"(a[mf][3]),
                          "r"(b[nf][0]), "r"(b[nf][1]));
        }
        if (ch < 7) {
            __syncthreads();
            stchunk((ch + 1) & 1);
            __syncthreads();
        }
    }

    // epilogue: plain stores into this split-K slab (no atomics)
    const int m0 = mb * 64, gid = lane >> 2, q = lane & 3;
#pragma unroll
    for (int mf = 0; mf < 2; ++mf) {
        int row = m0 + wm * 32 + mf * 16 + gid;
#pragma unroll
        for (int nf = 0; nf < 4; ++nf) {
            int coln = n0 + wn * 32 + nf * 8 + 2 * q;
            *(float2*)&g_P[kb][row][coln]     = make_float2(acc[mf][nf][0], acc[mf][nf][1]);
            *(float2*)&g_P[kb][row + 8][coln] = make_float2(acc[mf][nf][2], acc[mf][nf][3]);
        }
    }
}

// ---------------- k3: per-row max violation, mean into out ----------------
__global__ __launch_bounds__(1024) void k3_loss(const float* __restrict__ bvec,
                                                const int* __restrict__ targets,
                                                float* __restrict__ out) {
    const int i = blockIdx.x;
    const int c = threadIdx.x;
    const int t = targets[i];
    __shared__ float s_corr, s_nt;
    __shared__ float red[32];

    if (c == 0) {
        float sc = bvec[t];
#pragma unroll
        for (int s = 0; s < SPLITK; ++s) sc += g_P[s][i][t];
        s_corr = sc;
        s_nt = g_norm[t];
    }
    __syncthreads();

    float v = 0.0f;
    if (c < Cn && c != t) {
        float lg = bvec[c], gr = 0.0f;
#pragma unroll
        for (int s = 0; s < SPLITK; ++s) {
            lg += g_P[s][i][c];
            gr += g_P[s][i + 128][c];
        }
        float ss = g_norm[c] + s_nt - 2.0f * gr;
        float dn = sqrtf(ss + EPS_) + EPS_;
        v = fmaxf(0.0f, GAMMA_ + (lg - s_corr) / dn);
    }
#pragma unroll
    for (int o = 16; o; o >>= 1) v = fmaxf(v, __shfl_xor_sync(~0u, v, o));
    if ((c & 31) == 0) red[c >> 5] = v;
    __syncthreads();
    if (c < 32) {
        float r = red[c];
#pragma unroll
        for (int o = 16; o; o >>= 1) r = fmaxf(r, __shfl_xor_sync(~0u, r, o));
        if (c == 0) atomicAdd(out, r * (1.0f / 128.0f));
    }
}

// ---------------- launch ----------------
extern "C" void kernel_launch(void* const* d_in, const int* in_sizes, int n_in,
                              void* d_out, int out_size) {
    const float* A = (const float*)d_in[0];        // [128,1024]
    const float* W = (const float*)d_in[1];        // [1024,1000]
    const float* b = (const float*)d_in[2];        // [1000]
    const int* targets = (const int*)d_in[3];      // [128]
    float* out = (float*)d_out;

    k1_prep<<<385, 128>>>(W, targets, out);
    k2_gemm<<<dim3(16, 5, SPLITK), 128>>>(A, W);
    k3_loss<<<Bn, 1024>>>(b, targets, out);
}